// round 9
// baseline (speedup 1.0000x reference)
#include <cuda_runtime.h>
#include <math.h>

namespace {

constexpr int B = 32, H = 512, W = 512;
constexpr int TX = 128, TY = 32, NT = 512;
constexpr int MR = 48, MC = 148;   // channel-sum tile: rows y0-8..y0+39, cols x0-8..x0+139
constexpr int MG = MC / 4;         // 37 float4 groups per mean row
constexpr int TR = 34;             // vblur rows: y0-1..y0+32
constexpr int BC = 132;            // blur cols: x0-1..x0+130

// 15-tap Gaussian (sigma=2, 17-tap minus the two 6.7e-5 edge taps; ~2.7e-4 scale err)
__device__ constexpr float GW15[15] = {
    4.3634800e-04f, 2.2159640e-03f, 8.7643070e-03f, 2.6995960e-02f,
    6.4759940e-02f, 1.2098749e-01f, 1.7603580e-01f, 1.9947466e-01f,
    1.7603580e-01f, 1.2098749e-01f, 6.4759940e-02f, 2.6995960e-02f,
    8.7643070e-03f, 2.2159640e-03f, 4.3634800e-04f
};

__global__ void __launch_bounds__(NT, 3)
k_fused(const float* __restrict__ x, float* __restrict__ out)
{
    __shared__ __align__(16) float s_a[MR * MC];   // channel sum; later aliased as blur tile
    __shared__ __align__(16) float s_t[TR * MC];   // vblur output
    float* s_bl = s_a;                             // blur tile [TR][BC], reuses s_a

    const int x0 = blockIdx.x * TX;
    const int y0 = blockIdx.y * TY;
    const int b  = blockIdx.z;
    const int tid = threadIdx.x;
    const float* bp = x + (size_t)b * 3 * H * W;

    // ---- Phase 1: channel-sum tile with halo (y reflect + x reflect, Gaussian) ----
    const bool xint = (x0 >= 8) && (x0 + 140 <= W);
#pragma unroll
    for (int it = 0; it < 4; it++) {
        int idx = tid + it * NT;
        if (idx >= MR * MG) break;
        int rr = idx / MG;
        int g  = idx - rr * MG;
        int my = y0 - 8 + rr;
        my = (my < 0) ? (-my - 1) : my;            // reflect top
        my = (my > H - 1) ? (2 * H - 1 - my) : my; // reflect bottom
        int xs = x0 - 8 + 4 * g;
        float4 m;
        if (xint || (xs >= 0 && xs + 4 <= W)) {
            const float* p = bp + (size_t)my * W + xs;
            float4 a = *reinterpret_cast<const float4*>(p);
            float4 c = *reinterpret_cast<const float4*>(p + H * W);
            float4 d = *reinterpret_cast<const float4*>(p + 2 * H * W);
            m = make_float4(a.x + c.x + d.x, a.y + c.y + d.y,
                            a.z + c.z + d.z, a.w + c.w + d.w);
        } else {
            float mm[4];
#pragma unroll
            for (int e = 0; e < 4; e++) {
                int xx = xs + e;
                xx = (xx < 0) ? (-xx - 1) : xx;
                xx = (xx > W - 1) ? (2 * W - 1 - xx) : xx;
                const float* p = bp + (size_t)my * W + xx;
                mm[e] = p[0] + p[H * W] + p[2 * H * W];
            }
            m = make_float4(mm[0], mm[1], mm[2], mm[3]);
        }
        *reinterpret_cast<float4*>(&s_a[rr * MC + 4 * g]) = m;
    }
    __syncthreads();

    // ---- Phase 2: vertical 15-tap blur, 6-row float2 strips (20 LDS.64 / 6 rows) ----
    if (tid < 6 * 74) {                       // 444 active: 6 strips x 74 float2 groups
        int strip = tid / 74;
        int g     = tid - strip * 74;
        int r0s   = strip * 6;
        float2 acc[6];
#pragma unroll
        for (int i = 0; i < 6; i++) acc[i] = make_float2(0.f, 0.f);
#pragma unroll
        for (int k = 0; k < 20; k++) {
            int rw = r0s + k; if (rw > MR - 1) rw = MR - 1;   // clamp (tail strip only)
            float2 v = *reinterpret_cast<const float2*>(&s_a[rw * MC + 2 * g]);
#pragma unroll
            for (int i = 0; i < 6; i++) {
                int kk = k - i;
                if (kk >= 0 && kk <= 14) {
                    const float w = GW15[kk] * (1.0f / 3.0f);
                    acc[i].x += w * v.x; acc[i].y += w * v.y;
                }
            }
        }
#pragma unroll
        for (int i = 0; i < 6; i++) {
            int rr = r0s + i;
            if (rr < TR) {
                float2 av = acc[i];
                int yy = y0 - 1 + rr;                       // Sobel zero-pad in y
                if (yy < 0 || yy >= H) av = make_float2(0.f, 0.f);
                *reinterpret_cast<float2*>(&s_t[rr * MC + 2 * g]) = av;
            }
        }
    }
    __syncthreads();

    // ---- Phase 3: horizontal 15-tap blur, 6-wide float2 items (10 LDS.64 / 6 out) ----
#pragma unroll
    for (int it = 0; it < 2; it++) {
        int idx = tid + it * NT;
        if (idx >= TR * 22) break;            // 748 items
        int rr = idx / 22;
        int g  = idx - rr * 22;
        const float* src = &s_t[rr * MC + 6 * g];
        float c[20];
#pragma unroll
        for (int j = 0; j < 10; j++) {
            float2 v = *reinterpret_cast<const float2*>(src + 2 * j);
            c[2 * j] = v.x; c[2 * j + 1] = v.y;
        }
        float r[6];
#pragma unroll
        for (int o = 0; o < 6; o++) {
            float acc = 0.f;
#pragma unroll
            for (int k = 0; k < 15; k++) acc += GW15[k] * c[o + k];
            r[o] = acc;
        }
        int xb = x0 - 1 + 6 * g;                            // Sobel zero-pad in x
#pragma unroll
        for (int o = 0; o < 6; o++) {
            int xx = xb + o;
            if (xx < 0 || xx >= W) r[o] = 0.f;
        }
        float* dst = &s_bl[rr * BC + 6 * g];
        *reinterpret_cast<float2*>(dst)     = make_float2(r[0], r[1]);
        *reinterpret_cast<float2*>(dst + 2) = make_float2(r[2], r[3]);
        *reinterpret_cast<float2*>(dst + 4) = make_float2(r[4], r[5]);
    }
    __syncthreads();

    // ---- Phase 4: Sobel + magnitude, 4-wide x 2-tall, exactly 1 item/thread ----
    {
        int rp = tid >> 5;                  // 0..15
        int g  = tid & 31;                  // col group
        int r  = rp * 2;                    // local output row 0..30
        int jc = 4 * g;
        const float* p0 = &s_bl[(r    ) * BC + jc];
        const float* p1 = &s_bl[(r + 1) * BC + jc];
        const float* p2 = &s_bl[(r + 2) * BC + jc];
        const float* p3 = &s_bl[(r + 3) * BC + jc];
        float4 a0 = *reinterpret_cast<const float4*>(p0);
        float4 a1 = *reinterpret_cast<const float4*>(p0 + 4);
        float4 b0 = *reinterpret_cast<const float4*>(p1);
        float4 b1 = *reinterpret_cast<const float4*>(p1 + 4);
        float4 c0 = *reinterpret_cast<const float4*>(p2);
        float4 c1 = *reinterpret_cast<const float4*>(p2 + 4);
        float4 d0 = *reinterpret_cast<const float4*>(p3);
        float4 d1 = *reinterpret_cast<const float4*>(p3 + 4);

        float av[6] = { a0.x, a0.y, a0.z, a0.w, a1.x, a1.y };
        float bv[6] = { b0.x, b0.y, b0.z, b0.w, b1.x, b1.y };
        float cv[6] = { c0.x, c0.y, c0.z, c0.w, c1.x, c1.y };
        float dv[6] = { d0.x, d0.y, d0.z, d0.w, d1.x, d1.y };

        float4 o_top, o_bot;
        float* ot  = &o_top.x;
        float* obt = &o_bot.x;
#pragma unroll
        for (int q = 0; q < 4; q++) {
            float gx = (cv[q] - av[q]) + 2.0f * (cv[q + 1] - av[q + 1]) + (cv[q + 2] - av[q + 2]);
            float gy = (av[q + 2] - av[q]) + 2.0f * (bv[q + 2] - bv[q]) + (cv[q + 2] - cv[q]);
            float m = gx * gx + gy * gy;
            float o = m * rsqrtf(m);
            ot[q] = (m > 0.f) ? o : 0.f;

            float gx2 = (dv[q] - bv[q]) + 2.0f * (dv[q + 1] - bv[q + 1]) + (dv[q + 2] - bv[q + 2]);
            float gy2 = (bv[q + 2] - bv[q]) + 2.0f * (cv[q + 2] - cv[q]) + (dv[q + 2] - dv[q]);
            float m2 = gx2 * gx2 + gy2 * gy2;
            float o2 = m2 * rsqrtf(m2);
            obt[q] = (m2 > 0.f) ? o2 : 0.f;
        }
        float* ob = out + ((size_t)b * H + y0) * W + x0;
        *reinterpret_cast<float4*>(ob + (size_t)(r    ) * W + jc) = o_top;
        *reinterpret_cast<float4*>(ob + (size_t)(r + 1) * W + jc) = o_bot;
    }
}

} // namespace

extern "C" void kernel_launch(void* const* d_in, const int* in_sizes, int n_in,
                              void* d_out, int out_size)
{
    const float* x = (const float*)d_in[0];
    float* out = (float*)d_out;
    (void)in_sizes; (void)n_in; (void)out_size;

    dim3 grid(W / TX, H / TY, B);   // (4, 16, 32) = 2048 blocks
    k_fused<<<grid, NT>>>(x, out);
}

// round 10
// speedup vs baseline: 1.3850x; 1.3850x over previous
#include <cuda_runtime.h>
#include <math.h>

namespace {

constexpr int B = 32, H = 512, W = 512;
constexpr int TX = 128, TY = 32, NT = 512;
constexpr int MR = 48, MC = 148;   // channel-sum tile: rows y0-8..y0+39, cols x0-8..x0+139
constexpr int MG = MC / 4;         // 37 float4 groups per mean row
constexpr int TR = 34;             // vblur rows: y0-1..y0+32
constexpr int BC = 132;            // blur cols: x0-1..x0+130

// 15-tap Gaussian (sigma=2, 17-tap minus the two 6.7e-5 edge taps; ~2.7e-4 scale err)
__device__ constexpr float GW15[15] = {
    4.3634800e-04f, 2.2159640e-03f, 8.7643070e-03f, 2.6995960e-02f,
    6.4759940e-02f, 1.2098749e-01f, 1.7603580e-01f, 1.9947466e-01f,
    1.7603580e-01f, 1.2098749e-01f, 6.4759940e-02f, 2.6995960e-02f,
    8.7643070e-03f, 2.2159640e-03f, 4.3634800e-04f
};

__global__ void __launch_bounds__(NT, 3)
k_fused(const float* __restrict__ x, float* __restrict__ out)
{
    __shared__ __align__(16) float s_a[MR * MC];   // channel sum; later aliased as blur tile
    __shared__ __align__(16) float s_t[TR * MC];   // vblur output
    float* s_bl = s_a;                             // blur tile [TR][BC], reuses s_a

    const int x0 = blockIdx.x * TX;
    const int y0 = blockIdx.y * TY;
    const int b  = blockIdx.z;
    const int tid = threadIdx.x;
    const float* bp = x + (size_t)b * 3 * H * W;

    // ---- Phase 1: channel-sum tile with halo (y reflect + x reflect, Gaussian) ----
    const bool xint = (x0 >= 8) && (x0 + 140 <= W);
#pragma unroll
    for (int it = 0; it < 4; it++) {
        int idx = tid + it * NT;
        if (idx >= MR * MG) break;
        int rr = idx / MG;
        int g  = idx - rr * MG;
        int my = y0 - 8 + rr;
        my = (my < 0) ? (-my - 1) : my;            // reflect top
        my = (my > H - 1) ? (2 * H - 1 - my) : my; // reflect bottom
        int xs = x0 - 8 + 4 * g;
        float4 m;
        if (xint || (xs >= 0 && xs + 4 <= W)) {
            const float* p = bp + (size_t)my * W + xs;
            float4 a = *reinterpret_cast<const float4*>(p);
            float4 c = *reinterpret_cast<const float4*>(p + H * W);
            float4 d = *reinterpret_cast<const float4*>(p + 2 * H * W);
            m = make_float4(a.x + c.x + d.x, a.y + c.y + d.y,
                            a.z + c.z + d.z, a.w + c.w + d.w);
        } else {
            float mm[4];
#pragma unroll
            for (int e = 0; e < 4; e++) {
                int xx = xs + e;
                xx = (xx < 0) ? (-xx - 1) : xx;
                xx = (xx > W - 1) ? (2 * W - 1 - xx) : xx;
                const float* p = bp + (size_t)my * W + xx;
                mm[e] = p[0] + p[H * W] + p[2 * H * W];
            }
            m = make_float4(mm[0], mm[1], mm[2], mm[3]);
        }
        *reinterpret_cast<float4*>(&s_a[rr * MC + 4 * g]) = m;
    }
    __syncthreads();

    // ---- Phase 2: vertical 15-tap blur, 4-row float4 strips (18 LDS.128 / 4 rows) ----
    if (tid < 9 * MG) {                       // 333 active: 9 strips x 37 float4 groups
        int strip = tid / MG;
        int g     = tid - strip * MG;
        int r0s   = strip * 4;
        float4 a0 = make_float4(0.f, 0.f, 0.f, 0.f), a1 = a0, a2 = a0, a3 = a0;
#pragma unroll
        for (int k = 0; k < 18; k++) {
            int rw = r0s + k; rw = (rw > MR - 1) ? (MR - 1) : rw;  // clamp (tail strip only)
            float4 v = *reinterpret_cast<const float4*>(&s_a[rw * MC + 4 * g]);
            if (k <= 14) {
                const float w = GW15[k] * (1.0f / 3.0f);
                a0.x += w * v.x; a0.y += w * v.y; a0.z += w * v.z; a0.w += w * v.w;
            }
            if (k >= 1 && k <= 15) {
                const float w = GW15[k - 1] * (1.0f / 3.0f);
                a1.x += w * v.x; a1.y += w * v.y; a1.z += w * v.z; a1.w += w * v.w;
            }
            if (k >= 2 && k <= 16) {
                const float w = GW15[k - 2] * (1.0f / 3.0f);
                a2.x += w * v.x; a2.y += w * v.y; a2.z += w * v.z; a2.w += w * v.w;
            }
            if (k >= 3) {
                const float w = GW15[k - 3] * (1.0f / 3.0f);
                a3.x += w * v.x; a3.y += w * v.y; a3.z += w * v.z; a3.w += w * v.w;
            }
        }
#pragma unroll
        for (int i = 0; i < 4; i++) {
            int rr = r0s + i;
            if (rr < TR) {
                float4 av = (i == 0) ? a0 : ((i == 1) ? a1 : ((i == 2) ? a2 : a3));
                int yy = y0 - 1 + rr;                       // Sobel zero-pad in y
                if (yy < 0 || yy >= H) av = make_float4(0.f, 0.f, 0.f, 0.f);
                *reinterpret_cast<float4*>(&s_t[rr * MC + 4 * g]) = av;
            }
        }
    }
    __syncthreads();

    // ---- Phase 3: horizontal 15-tap blur, 4 outputs/item via 5 LDS.128 ----
#pragma unroll
    for (int it = 0; it < 3; it++) {
        int idx = tid + it * NT;
        if (idx >= TR * 33) break;
        int rr = idx / 33;
        int g  = idx - rr * 33;
        const float* src = &s_t[rr * MC + 4 * g];
        float4 v0 = *reinterpret_cast<const float4*>(src);
        float4 v1 = *reinterpret_cast<const float4*>(src + 4);
        float4 v2 = *reinterpret_cast<const float4*>(src + 8);
        float4 v3 = *reinterpret_cast<const float4*>(src + 12);
        float4 v4 = *reinterpret_cast<const float4*>(src + 16);
        float c[20] = { v0.x, v0.y, v0.z, v0.w,
                        v1.x, v1.y, v1.z, v1.w,
                        v2.x, v2.y, v2.z, v2.w,
                        v3.x, v3.y, v3.z, v3.w,
                        v4.x, v4.y, v4.z, v4.w };
        float r0 = 0.f, r1 = 0.f, r2 = 0.f, r3 = 0.f;
#pragma unroll
        for (int k = 0; k < 15; k++) {
            r0 += GW15[k] * c[k];
            r1 += GW15[k] * c[k + 1];
            r2 += GW15[k] * c[k + 2];
            r3 += GW15[k] * c[k + 3];
        }
        int xb = x0 - 1 + 4 * g;                           // Sobel zero-pad in x
        if (xb < 0 || xb >= W) r0 = 0.f;
        if (xb + 1 >= W)       r1 = 0.f;
        if (xb + 2 >= W)       r2 = 0.f;
        if (xb + 3 >= W)       r3 = 0.f;
        *reinterpret_cast<float4*>(&s_bl[rr * BC + 4 * g]) =
            make_float4(r0, r1, r2, r3);
    }
    __syncthreads();

    // ---- Phase 4: Sobel + magnitude, 4-wide x 2-tall, exactly 1 item/thread ----
    {
        int rp = tid >> 5;                  // 0..15
        int g  = tid & 31;                  // col group
        int r  = rp * 2;                    // local output row 0..30
        int jc = 4 * g;
        const float* p0 = &s_bl[(r    ) * BC + jc];
        const float* p1 = &s_bl[(r + 1) * BC + jc];
        const float* p2 = &s_bl[(r + 2) * BC + jc];
        const float* p3 = &s_bl[(r + 3) * BC + jc];
        float4 a0 = *reinterpret_cast<const float4*>(p0);
        float4 a1 = *reinterpret_cast<const float4*>(p0 + 4);
        float4 b0 = *reinterpret_cast<const float4*>(p1);
        float4 b1 = *reinterpret_cast<const float4*>(p1 + 4);
        float4 c0 = *reinterpret_cast<const float4*>(p2);
        float4 c1 = *reinterpret_cast<const float4*>(p2 + 4);
        float4 d0 = *reinterpret_cast<const float4*>(p3);
        float4 d1 = *reinterpret_cast<const float4*>(p3 + 4);

        float av[6] = { a0.x, a0.y, a0.z, a0.w, a1.x, a1.y };
        float bv[6] = { b0.x, b0.y, b0.z, b0.w, b1.x, b1.y };
        float cv[6] = { c0.x, c0.y, c0.z, c0.w, c1.x, c1.y };
        float dv[6] = { d0.x, d0.y, d0.z, d0.w, d1.x, d1.y };

        float4 o_top, o_bot;
        float* ot  = &o_top.x;
        float* obt = &o_bot.x;
#pragma unroll
        for (int q = 0; q < 4; q++) {
            float gx = (cv[q] - av[q]) + 2.0f * (cv[q + 1] - av[q + 1]) + (cv[q + 2] - av[q + 2]);
            float gy = (av[q + 2] - av[q]) + 2.0f * (bv[q + 2] - bv[q]) + (cv[q + 2] - cv[q]);
            float m = gx * gx + gy * gy;
            float o = m * rsqrtf(m);
            ot[q] = (m > 0.f) ? o : 0.f;

            float gx2 = (dv[q] - bv[q]) + 2.0f * (dv[q + 1] - bv[q + 1]) + (dv[q + 2] - bv[q + 2]);
            float gy2 = (bv[q + 2] - bv[q]) + 2.0f * (cv[q + 2] - cv[q]) + (dv[q + 2] - dv[q]);
            float m2 = gx2 * gx2 + gy2 * gy2;
            float o2 = m2 * rsqrtf(m2);
            obt[q] = (m2 > 0.f) ? o2 : 0.f;
        }
        float* ob = out + ((size_t)b * H + y0) * W + x0;
        *reinterpret_cast<float4*>(ob + (size_t)(r    ) * W + jc) = o_top;
        *reinterpret_cast<float4*>(ob + (size_t)(r + 1) * W + jc) = o_bot;
    }
}

} // namespace

extern "C" void kernel_launch(void* const* d_in, const int* in_sizes, int n_in,
                              void* d_out, int out_size)
{
    const float* x = (const float*)d_in[0];
    float* out = (float*)d_out;
    (void)in_sizes; (void)n_in; (void)out_size;

    dim3 grid(W / TX, H / TY, B);   // (4, 16, 32) = 2048 blocks
    k_fused<<<grid, NT>>>(x, out);
}

// round 11
// speedup vs baseline: 1.4182x; 1.0240x over previous
#include <cuda_runtime.h>
#include <math.h>

namespace {

constexpr int B = 32, H = 512, W = 512;
constexpr int TX = 128, TY = 32, NT = 512;
constexpr int MR = 48, MC = 148;   // channel-sum tile: rows y0-8..y0+39, cols x0-8..x0+139
constexpr int MG = MC / 4;         // 37 float4 groups per mean row
constexpr int TR = 34;             // vblur rows: y0-1..y0+32
constexpr int BC = 132;            // blur cols: x0-1..x0+130

// 15-tap Gaussian (sigma=2, 17-tap minus the two 6.7e-5 edge taps; ~2.7e-4 scale err)
__device__ constexpr float GW15[15] = {
    4.3634800e-04f, 2.2159640e-03f, 8.7643070e-03f, 2.6995960e-02f,
    6.4759940e-02f, 1.2098749e-01f, 1.7603580e-01f, 1.9947466e-01f,
    1.7603580e-01f, 1.2098749e-01f, 6.4759940e-02f, 2.6995960e-02f,
    8.7643070e-03f, 2.2159640e-03f, 4.3634800e-04f
};

__global__ void __launch_bounds__(NT, 4)
k_fused(const float* __restrict__ x, float* __restrict__ out)
{
    __shared__ __align__(16) float s_a[MR * MC];   // channel sum; later aliased as blur tile
    __shared__ __align__(16) float s_t[TR * MC];   // vblur output
    float* s_bl = s_a;                             // blur tile [TR][BC], reuses s_a

    const int x0 = blockIdx.x * TX;
    const int y0 = blockIdx.y * TY;
    const int b  = blockIdx.z;
    const int tid = threadIdx.x;
    const float* bp = x + (size_t)b * 3 * H * W;

    // ---- Phase 1: channel-sum tile with halo (y reflect + x reflect, Gaussian) ----
    const bool xint = (x0 >= 8) && (x0 + 140 <= W);
#pragma unroll
    for (int it = 0; it < 4; it++) {
        int idx = tid + it * NT;
        if (idx >= MR * MG) break;
        int rr = idx / MG;
        int g  = idx - rr * MG;
        int my = y0 - 8 + rr;
        my = (my < 0) ? (-my - 1) : my;            // reflect top
        my = (my > H - 1) ? (2 * H - 1 - my) : my; // reflect bottom
        int xs = x0 - 8 + 4 * g;
        float4 m;
        if (xint || (xs >= 0 && xs + 4 <= W)) {
            const float* p = bp + (size_t)my * W + xs;
            float4 a = *reinterpret_cast<const float4*>(p);
            float4 c = *reinterpret_cast<const float4*>(p + H * W);
            float4 d = *reinterpret_cast<const float4*>(p + 2 * H * W);
            m = make_float4(a.x + c.x + d.x, a.y + c.y + d.y,
                            a.z + c.z + d.z, a.w + c.w + d.w);
        } else {
            float mm[4];
#pragma unroll
            for (int e = 0; e < 4; e++) {
                int xx = xs + e;
                xx = (xx < 0) ? (-xx - 1) : xx;
                xx = (xx > W - 1) ? (2 * W - 1 - xx) : xx;
                const float* p = bp + (size_t)my * W + xx;
                mm[e] = p[0] + p[H * W] + p[2 * H * W];
            }
            m = make_float4(mm[0], mm[1], mm[2], mm[3]);
        }
        *reinterpret_cast<float4*>(&s_a[rr * MC + 4 * g]) = m;
    }
    __syncthreads();

    // ---- Phase 2: vertical 15-tap blur, 4-row float4 strips (18 LDS.128 / 4 rows) ----
    if (tid < 9 * MG) {                       // 333 active: 9 strips x 37 float4 groups
        int strip = tid / MG;
        int g     = tid - strip * MG;
        int r0s   = strip * 4;
        float4 a0 = make_float4(0.f, 0.f, 0.f, 0.f), a1 = a0, a2 = a0, a3 = a0;
#pragma unroll
        for (int k = 0; k < 18; k++) {
            int rw = r0s + k; rw = (rw > MR - 1) ? (MR - 1) : rw;  // clamp (tail strip only)
            float4 v = *reinterpret_cast<const float4*>(&s_a[rw * MC + 4 * g]);
            if (k <= 14) {
                const float w = GW15[k] * (1.0f / 3.0f);
                a0.x += w * v.x; a0.y += w * v.y; a0.z += w * v.z; a0.w += w * v.w;
            }
            if (k >= 1 && k <= 15) {
                const float w = GW15[k - 1] * (1.0f / 3.0f);
                a1.x += w * v.x; a1.y += w * v.y; a1.z += w * v.z; a1.w += w * v.w;
            }
            if (k >= 2 && k <= 16) {
                const float w = GW15[k - 2] * (1.0f / 3.0f);
                a2.x += w * v.x; a2.y += w * v.y; a2.z += w * v.z; a2.w += w * v.w;
            }
            if (k >= 3) {
                const float w = GW15[k - 3] * (1.0f / 3.0f);
                a3.x += w * v.x; a3.y += w * v.y; a3.z += w * v.z; a3.w += w * v.w;
            }
        }
#pragma unroll
        for (int i = 0; i < 4; i++) {
            int rr = r0s + i;
            if (rr < TR) {
                float4 av = (i == 0) ? a0 : ((i == 1) ? a1 : ((i == 2) ? a2 : a3));
                int yy = y0 - 1 + rr;                       // Sobel zero-pad in y
                if (yy < 0 || yy >= H) av = make_float4(0.f, 0.f, 0.f, 0.f);
                *reinterpret_cast<float4*>(&s_t[rr * MC + 4 * g]) = av;
            }
        }
    }
    __syncthreads();

    // ---- Phase 3: horizontal 15-tap blur, 4 outputs/item via 5 LDS.128 ----
    // Incremental accumulation: each loaded float4 is consumed immediately
    // (live set ~12 floats, keeps total regs <= 32 for 4 blocks/SM).
#pragma unroll
    for (int it = 0; it < 3; it++) {
        int idx = tid + it * NT;
        if (idx >= TR * 33) break;
        int rr = idx / 33;
        int g  = idx - rr * 33;
        const float* src = &s_t[rr * MC + 4 * g];
        float r[4] = { 0.f, 0.f, 0.f, 0.f };
#pragma unroll
        for (int j = 0; j < 5; j++) {
            float4 v = *reinterpret_cast<const float4*>(src + 4 * j);
            float cc[4] = { v.x, v.y, v.z, v.w };
#pragma unroll
            for (int e = 0; e < 4; e++) {
                const int i = 4 * j + e;
#pragma unroll
                for (int o = 0; o < 4; o++) {
                    const int k = i - o;
                    if (k >= 0 && k <= 14) r[o] += GW15[k] * cc[e];
                }
            }
        }
        int xb = x0 - 1 + 4 * g;                           // Sobel zero-pad in x
        if (xb < 0 || xb >= W) r[0] = 0.f;
        if (xb + 1 >= W)       r[1] = 0.f;
        if (xb + 2 >= W)       r[2] = 0.f;
        if (xb + 3 >= W)       r[3] = 0.f;
        *reinterpret_cast<float4*>(&s_bl[rr * BC + 4 * g]) =
            make_float4(r[0], r[1], r[2], r[3]);
    }
    __syncthreads();

    // ---- Phase 4: Sobel + magnitude, 4-wide x 2-tall, exactly 1 item/thread ----
    // Top row computed and stored before loading the 4th smem row (lower reg peak).
    {
        int rp = tid >> 5;                  // 0..15
        int g  = tid & 31;                  // col group
        int r  = rp * 2;                    // local output row 0..30
        int jc = 4 * g;
        const float* p0 = &s_bl[(r    ) * BC + jc];
        const float* p1 = &s_bl[(r + 1) * BC + jc];
        const float* p2 = &s_bl[(r + 2) * BC + jc];
        const float* p3 = &s_bl[(r + 3) * BC + jc];
        float* ob = out + ((size_t)b * H + y0) * W + x0;

        float4 a0 = *reinterpret_cast<const float4*>(p0);
        float4 a1 = *reinterpret_cast<const float4*>(p0 + 4);
        float4 b0 = *reinterpret_cast<const float4*>(p1);
        float4 b1 = *reinterpret_cast<const float4*>(p1 + 4);
        float4 c0 = *reinterpret_cast<const float4*>(p2);
        float4 c1 = *reinterpret_cast<const float4*>(p2 + 4);

        float av[6] = { a0.x, a0.y, a0.z, a0.w, a1.x, a1.y };
        float bv[6] = { b0.x, b0.y, b0.z, b0.w, b1.x, b1.y };
        float cv[6] = { c0.x, c0.y, c0.z, c0.w, c1.x, c1.y };

        float4 o_top;
        float* ot = &o_top.x;
#pragma unroll
        for (int q = 0; q < 4; q++) {
            float gx = (cv[q] - av[q]) + 2.0f * (cv[q + 1] - av[q + 1]) + (cv[q + 2] - av[q + 2]);
            float gy = (av[q + 2] - av[q]) + 2.0f * (bv[q + 2] - bv[q]) + (cv[q + 2] - cv[q]);
            float m = gx * gx + gy * gy;
            float o = m * rsqrtf(m);
            ot[q] = (m > 0.f) ? o : 0.f;
        }
        *reinterpret_cast<float4*>(ob + (size_t)r * W + jc) = o_top;

        float4 d0 = *reinterpret_cast<const float4*>(p3);
        float4 d1 = *reinterpret_cast<const float4*>(p3 + 4);
        float dv[6] = { d0.x, d0.y, d0.z, d0.w, d1.x, d1.y };

        float4 o_bot;
        float* obt = &o_bot.x;
#pragma unroll
        for (int q = 0; q < 4; q++) {
            float gx2 = (dv[q] - bv[q]) + 2.0f * (dv[q + 1] - bv[q + 1]) + (dv[q + 2] - bv[q + 2]);
            float gy2 = (bv[q + 2] - bv[q]) + 2.0f * (cv[q + 2] - cv[q]) + (dv[q + 2] - dv[q]);
            float m2 = gx2 * gx2 + gy2 * gy2;
            float o2 = m2 * rsqrtf(m2);
            obt[q] = (m2 > 0.f) ? o2 : 0.f;
        }
        *reinterpret_cast<float4*>(ob + (size_t)(r + 1) * W + jc) = o_bot;
    }
}

} // namespace

extern "C" void kernel_launch(void* const* d_in, const int* in_sizes, int n_in,
                              void* d_out, int out_size)
{
    const float* x = (const float*)d_in[0];
    float* out = (float*)d_out;
    (void)in_sizes; (void)n_in; (void)out_size;

    dim3 grid(W / TX, H / TY, B);   // (4, 16, 32) = 2048 blocks
    k_fused<<<grid, NT>>>(x, out);
}